// round 3
// baseline (speedup 1.0000x reference)
#include <cuda_runtime.h>
#include <stdint.h>

#define B_     2
#define N_     65536
#define M_     16384
#define K_     32
#define KP_    15
#define DIN_   64
#define DOUT_  128
#define SHADOW (-1000.0f)

// Scratch: features transposed to [B][N][Din] (33.5 MB) and the per-point
// weighted tensor [B*M][Kp*Din] (125.8 MB). Static __device__ arrays per the
// no-allocation rule.
__device__ float g_featT[(size_t)B_ * N_ * DIN_];
__device__ float g_weighted[(size_t)B_ * M_ * KP_ * DIN_];

// ---------------------------------------------------------------------------
// Kernel 1: transpose features [B][Din][N] -> g_featT [B][N][Din]
// ---------------------------------------------------------------------------
__global__ void transpose_feat_kernel(const float* __restrict__ f)
{
    __shared__ float tile[32][33];
    const int b  = blockIdx.z;
    const int n0 = blockIdx.x * 32;
    const int d0 = blockIdx.y * 32;
    const int x = threadIdx.x;   // 0..31
    const int y = threadIdx.y;   // 0..7

    #pragma unroll
    for (int i = y; i < 32; i += 8)
        tile[i][x] = f[((size_t)b * DIN_ + (d0 + i)) * N_ + n0 + x];
    __syncthreads();
    #pragma unroll
    for (int i = y; i < 32; i += 8)
        g_featT[((size_t)b * N_ + (n0 + i)) * DIN_ + d0 + x] = tile[x][i];
}

// ---------------------------------------------------------------------------
// Kernel 2: per point (b,m): gather neighbors, compute kernel weights w[K][Kp],
// then weighted[p][d] = sum_k w[k][p] * feat[k][d]  ->  g_weighted row (960)
// NOTE: neighbor_indices is int32 (JAX canonicalizes int64 -> int32).
// ---------------------------------------------------------------------------
__global__ __launch_bounds__(256)
void kpconv_weighted_kernel(const float* __restrict__ points_xyz,
                            const float* __restrict__ center_xyz,
                            const int* __restrict__ nidx,
                            const float* __restrict__ kernel_points)
{
    const int bm = blockIdx.x;          // 0 .. B*M-1
    const int b  = bm >> 14;            // M = 16384
    const int t  = threadIdx.x;

    __shared__ int   s_idx[K_];
    __shared__ float s_rx[K_], s_ry[K_], s_rz[K_];
    __shared__ float s_w[K_][KP_];
    __shared__ float s_feat[K_][DIN_];
    __shared__ float s_md;

    const float cx = center_xyz[bm * 3 + 0];
    const float cy = center_xyz[bm * 3 + 1];
    const float cz = center_xyz[bm * 3 + 2];

    if (t < K_) {
        const int ii = nidx[(size_t)bm * K_ + t];
        s_idx[t] = ii;
        float px, py, pz;
        if ((unsigned)ii >= (unsigned)N_) { px = SHADOW; py = SHADOW; pz = SHADOW; }
        else {
            const float* pp = points_xyz + ((size_t)b * N_ + ii) * 3;
            px = pp[0]; py = pp[1]; pz = pp[2];
        }
        const float rx = px - cx, ry = py - cy, rz = pz - cz;
        s_rx[t] = rx; s_ry[t] = ry; s_rz[t] = rz;
        float d = sqrtf(rx * rx + ry * ry + rz * rz);
        #pragma unroll
        for (int o = 16; o; o >>= 1)
            d = fmaxf(d, __shfl_xor_sync(0xffffffffu, d, o));
        if (t == 0) s_md = d;
    }
    __syncthreads();

    const float mdist     = s_md;
    const float inv_sigma = 1.0f / (mdist / 2.1f + 1e-5f);

    // w[k][p] = max(0, 1 - |rel_k - kp_p * mdist| / sigma)
    for (int e = t; e < K_ * KP_; e += 256) {
        const int k = e / KP_;
        const int p = e - k * KP_;
        const float kx = kernel_points[p * 3 + 0] * mdist;
        const float ky = kernel_points[p * 3 + 1] * mdist;
        const float kz = kernel_points[p * 3 + 2] * mdist;
        const float dx = s_rx[k] - kx;
        const float dy = s_ry[k] - ky;
        const float dz = s_rz[k] - kz;
        const float w  = 1.0f - sqrtf(dx * dx + dy * dy + dz * dz) * inv_sigma;
        s_w[k][p] = fmaxf(w, 0.0f);
    }

    // gather features: neighbor rows are contiguous (256B each) in g_featT
    for (int e = t; e < K_ * DIN_; e += 256) {
        const int k = e >> 6, d = e & 63;
        const int ii = s_idx[k];
        s_feat[k][d] = ((unsigned)ii >= (unsigned)N_)
                         ? 0.0f
                         : g_featT[((size_t)b * N_ + ii) * DIN_ + d];
    }
    __syncthreads();

    // weighted[p][d]: 240 active threads; each owns one p and a float4 of d.
    if (t < 240) {
        const int p  = t % 15;
        const int d4 = t / 15;           // 0..15
        float4 acc = make_float4(0.f, 0.f, 0.f, 0.f);
        #pragma unroll
        for (int k = 0; k < K_; k++) {
            const float  w = s_w[k][p];
            const float4 f = *(const float4*)&s_feat[k][d4 * 4];
            acc.x += w * f.x; acc.y += w * f.y;
            acc.z += w * f.z; acc.w += w * f.w;
        }
        *(float4*)&g_weighted[(size_t)bm * (KP_ * DIN_) + p * DIN_ + d4 * 4] = acc;
    }
}

// ---------------------------------------------------------------------------
// Kernel 3: SGEMM  C[r][o] = A[r][pd] * W[pd][o]
//   A = g_weighted [32768 x 960], W = weights [960 x 128]
//   output written as out[b][o][m] (coalesced along m via smem transpose)
// ---------------------------------------------------------------------------
__global__ __launch_bounds__(256, 2)
void kpconv_gemm_kernel(const float* __restrict__ W, float* __restrict__ out)
{
    __shared__ float As[128][20];    // [row][kk], pad to 20 (float4-aligned)
    __shared__ float Bs[16][128];
    __shared__ float Cs[32][129];

    const int tid = threadIdx.x;
    const int tx  = tid & 15;        // 0..15 -> output col group
    const int ty  = tid >> 4;        // 0..15 -> output row group
    const size_t rowBase = (size_t)blockIdx.x * 128;

    float acc[8][8];
    #pragma unroll
    for (int i = 0; i < 8; i++)
        #pragma unroll
        for (int j = 0; j < 8; j++) acc[i][j] = 0.0f;

    for (int k0 = 0; k0 < 960; k0 += 16) {
        // load A tile 128x16 (512 float4) and B tile 16x128 (512 float4)
        #pragma unroll
        for (int l = 0; l < 2; l++) {
            const int v  = tid + l * 256;
            const int r  = v >> 2, kv = v & 3;
            *(float4*)&As[r][kv * 4] =
                *(const float4*)&g_weighted[(rowBase + r) * 960 + k0 + kv * 4];
            const int kk = v >> 5, ov = v & 31;
            *(float4*)&Bs[kk][ov * 4] =
                *(const float4*)&W[(size_t)(k0 + kk) * 128 + ov * 4];
        }
        __syncthreads();

        #pragma unroll
        for (int kk = 0; kk < 16; kk++) {
            float a_frag[8], b_frag[8];
            #pragma unroll
            for (int i = 0; i < 8; i++) a_frag[i] = As[ty * 8 + i][kk];
            *(float4*)&b_frag[0] = *(const float4*)&Bs[kk][tx * 8];
            *(float4*)&b_frag[4] = *(const float4*)&Bs[kk][tx * 8 + 4];
            #pragma unroll
            for (int i = 0; i < 8; i++)
                #pragma unroll
                for (int j = 0; j < 8; j++)
                    acc[i][j] += a_frag[i] * b_frag[j];
        }
        __syncthreads();
    }

    // write out[b][o][m]: chunked transpose through Cs for coalesced m-stores
    const int bb    = (int)(rowBase >> 14);     // rowBase / M
    const int mBase = (int)(rowBase & 16383);   // rowBase % M
    #pragma unroll
    for (int chunk = 0; chunk < 4; chunk++) {
        if (chunk) __syncthreads();
        if ((tx >> 2) == chunk) {
            const int txl = tx & 3;
            #pragma unroll
            for (int i = 0; i < 8; i++)
                #pragma unroll
                for (int j = 0; j < 8; j++)
                    Cs[txl * 8 + j][ty * 8 + i] = acc[i][j];
        }
        __syncthreads();
        #pragma unroll
        for (int l = 0; l < 16; l++) {
            const int e  = tid + l * 256;
            const int ol = e >> 7, r = e & 127;
            out[((size_t)bb * DOUT_ + chunk * 32 + ol) * M_ + mBase + r] = Cs[ol][r];
        }
    }
}

// ---------------------------------------------------------------------------
extern "C" void kernel_launch(void* const* d_in, const int* in_sizes, int n_in,
                              void* d_out, int out_size)
{
    // Dispatch inputs by element count (all six are pairwise distinct) so we
    // are immune to metadata ordering:
    //   points_xyz       : 2*65536*3    =   393216 f32
    //   features         : 2*64*65536   =  8388608 f32
    //   center_xyz       : 2*16384*3    =    98304 f32
    //   neighbor_indices : 2*16384*32   =  1048576 i32 (JAX canonicalizes i64->i32)
    //   kernel_points    : 15*3         =       45 f32
    //   weights          : 15*64*128    =   122880 f32
    const float* points_xyz    = nullptr;
    const float* features      = nullptr;
    const float* center_xyz    = nullptr;
    const int*   neighbor_idx  = nullptr;
    const float* kernel_points = nullptr;
    const float* weights       = nullptr;

    for (int i = 0; i < n_in; i++) {
        switch (in_sizes[i]) {
            case 393216:  points_xyz    = (const float*)d_in[i]; break;
            case 8388608: features      = (const float*)d_in[i]; break;
            case 98304:   center_xyz    = (const float*)d_in[i]; break;
            case 1048576: neighbor_idx  = (const int*)d_in[i];   break;
            case 45:      kernel_points = (const float*)d_in[i]; break;
            case 122880:  weights       = (const float*)d_in[i]; break;
            default: break;
        }
    }
    float* out = (float*)d_out;

    dim3 g1(N_ / 32, DIN_ / 32, B_);
    transpose_feat_kernel<<<g1, dim3(32, 8)>>>(features);

    kpconv_weighted_kernel<<<B_ * M_, 256>>>(points_xyz, center_xyz,
                                             neighbor_idx, kernel_points);

    kpconv_gemm_kernel<<<(B_ * M_) / 128, 256>>>(weights, out);
}

// round 5
// speedup vs baseline: 1.4527x; 1.4527x over previous
#include <cuda_runtime.h>
#include <cuda_bf16.h>
#include <stdint.h>

#define B_     2
#define N_     65536
#define M_     16384
#define K_     32
#define KP_    15
#define DIN_   64
#define DOUT_  128
#define KTOT   960           // KP_*DIN_
#define SHADOW (-1000.0f)

// ---------------------------------------------------------------------------
// Scratch (__device__ globals per no-allocation rule)
// ---------------------------------------------------------------------------
__device__ float g_featT[(size_t)B_ * N_ * DIN_];                       // 33.5 MB
__device__ __align__(16) __nv_bfloat16 g_whi[(size_t)B_ * M_ * KTOT];   // 60 MB
__device__ __align__(16) __nv_bfloat16 g_wlo[(size_t)B_ * M_ * KTOT];   // 60 MB
__device__ __align__(16) __nv_bfloat16 g_bhi[DOUT_ * KTOT];             // W^T hi
__device__ __align__(16) __nv_bfloat16 g_blo[DOUT_ * KTOT];             // W^T lo

// ---------------------------------------------------------------------------
// helpers
// ---------------------------------------------------------------------------
__device__ __forceinline__ uint32_t smem_u32(const void* p) {
    uint32_t a;
    asm("{ .reg .u64 t; cvta.to.shared.u64 t, %1; cvt.u32.u64 %0, t; }"
        : "=r"(a) : "l"(p));
    return a;
}
__device__ __forceinline__ void ldsm4(uint32_t& r0, uint32_t& r1,
                                      uint32_t& r2, uint32_t& r3, uint32_t addr) {
    asm volatile("ldmatrix.sync.aligned.m8n8.x4.shared.b16 {%0,%1,%2,%3}, [%4];"
                 : "=r"(r0), "=r"(r1), "=r"(r2), "=r"(r3) : "r"(addr));
}
__device__ __forceinline__ void mma16816(float* c, const uint32_t* a,
                                         const uint32_t* b) {
    asm volatile("mma.sync.aligned.m16n8k16.row.col.f32.bf16.bf16.f32 "
                 "{%0,%1,%2,%3}, {%4,%5,%6,%7}, {%8,%9}, {%0,%1,%2,%3};"
                 : "+f"(c[0]), "+f"(c[1]), "+f"(c[2]), "+f"(c[3])
                 : "r"(a[0]), "r"(a[1]), "r"(a[2]), "r"(a[3]),
                   "r"(b[0]), "r"(b[1]));
}

// ---------------------------------------------------------------------------
// Kernel 1: transpose features [B][Din][N] -> g_featT [B][N][Din]
// ---------------------------------------------------------------------------
__global__ void transpose_feat_kernel(const float* __restrict__ f)
{
    __shared__ float tile[32][33];
    const int b  = blockIdx.z;
    const int n0 = blockIdx.x * 32;
    const int d0 = blockIdx.y * 32;
    const int x = threadIdx.x, y = threadIdx.y;

    #pragma unroll
    for (int i = y; i < 32; i += 8)
        tile[i][x] = f[((size_t)b * DIN_ + (d0 + i)) * N_ + n0 + x];
    __syncthreads();
    #pragma unroll
    for (int i = y; i < 32; i += 8)
        g_featT[((size_t)b * N_ + (n0 + i)) * DIN_ + d0 + x] = tile[x][i];
}

// ---------------------------------------------------------------------------
// Kernel 1b: weights [Kp][Din][Dout] -> g_bhi/g_blo [Dout rows][KTOT cols]
// ---------------------------------------------------------------------------
__global__ void prep_w_kernel(const float* __restrict__ w)
{
    const int e = blockIdx.x * 256 + threadIdx.x;
    if (e >= KP_ * DIN_ * DOUT_) return;
    const int kp = e / DOUT_, o = e % DOUT_;
    const float v = w[e];
    const __nv_bfloat16 hi = __float2bfloat16(v);
    const __nv_bfloat16 lo = __float2bfloat16(v - __bfloat162float(hi));
    g_bhi[o * KTOT + kp] = hi;
    g_blo[o * KTOT + kp] = lo;
}

// ---------------------------------------------------------------------------
// Kernel 2: per point: gather, kernel weights, weighted[p][d] -> bf16 hi/lo
// NOTE: neighbor_indices is int32 (JAX canonicalizes int64 -> int32).
// ---------------------------------------------------------------------------
__global__ __launch_bounds__(256)
void kpconv_weighted_kernel(const float* __restrict__ points_xyz,
                            const float* __restrict__ center_xyz,
                            const int* __restrict__ nidx,
                            const float* __restrict__ kernel_points)
{
    const int bm = blockIdx.x;
    const int b  = bm >> 14;
    const int t  = threadIdx.x;

    __shared__ int   s_idx[K_];
    __shared__ float s_rx[K_], s_ry[K_], s_rz[K_];
    __shared__ float s_w[K_][KP_];
    __shared__ float s_feat[K_][DIN_];
    __shared__ float s_md;

    const float cx = center_xyz[bm * 3 + 0];
    const float cy = center_xyz[bm * 3 + 1];
    const float cz = center_xyz[bm * 3 + 2];

    if (t < K_) {
        const int ii = nidx[(size_t)bm * K_ + t];
        s_idx[t] = ii;
        float px, py, pz;
        if ((unsigned)ii >= (unsigned)N_) { px = SHADOW; py = SHADOW; pz = SHADOW; }
        else {
            const float* pp = points_xyz + ((size_t)b * N_ + ii) * 3;
            px = pp[0]; py = pp[1]; pz = pp[2];
        }
        const float rx = px - cx, ry = py - cy, rz = pz - cz;
        s_rx[t] = rx; s_ry[t] = ry; s_rz[t] = rz;
        float d = sqrtf(rx * rx + ry * ry + rz * rz);
        #pragma unroll
        for (int o = 16; o; o >>= 1)
            d = fmaxf(d, __shfl_xor_sync(0xffffffffu, d, o));
        if (t == 0) s_md = d;
    }
    __syncthreads();

    const float mdist     = s_md;
    const float inv_sigma = 1.0f / (mdist / 2.1f + 1e-5f);

    for (int e = t; e < K_ * KP_; e += 256) {
        const int k = e / KP_;
        const int p = e - k * KP_;
        const float kx = kernel_points[p * 3 + 0] * mdist;
        const float ky = kernel_points[p * 3 + 1] * mdist;
        const float kz = kernel_points[p * 3 + 2] * mdist;
        const float dx = s_rx[k] - kx;
        const float dy = s_ry[k] - ky;
        const float dz = s_rz[k] - kz;
        const float w  = 1.0f - sqrtf(dx * dx + dy * dy + dz * dz) * inv_sigma;
        s_w[k][p] = fmaxf(w, 0.0f);
    }

    // gather features (float4): rows contiguous (256B) in g_featT
    for (int e4 = t; e4 < K_ * DIN_ / 4; e4 += 256) {
        const int k  = e4 >> 4;
        const int d4 = e4 & 15;
        const int ii = s_idx[k];
        float4 v;
        if ((unsigned)ii >= (unsigned)N_) v = make_float4(0.f, 0.f, 0.f, 0.f);
        else v = *(const float4*)&g_featT[((size_t)b * N_ + ii) * DIN_ + d4 * 4];
        *(float4*)&s_feat[k][d4 * 4] = v;
    }
    __syncthreads();

    // weighted[p][d]: p = t>>4, d4 = t&15 (coalesced 8B stores per 16-thr group)
    if (t < 240) {
        const int p  = t >> 4;
        const int d4 = t & 15;
        float4 acc = make_float4(0.f, 0.f, 0.f, 0.f);
        #pragma unroll
        for (int k = 0; k < K_; k++) {
            const float  w = s_w[k][p];
            const float4 f = *(const float4*)&s_feat[k][d4 * 4];
            acc.x += w * f.x; acc.y += w * f.y;
            acc.z += w * f.z; acc.w += w * f.w;
        }
        const size_t off = (size_t)bm * KTOT + p * DIN_ + d4 * 4;
        const float a[4] = {acc.x, acc.y, acc.z, acc.w};
        __nv_bfloat16 h[4], l[4];
        #pragma unroll
        for (int i = 0; i < 4; i++) {
            h[i] = __float2bfloat16(a[i]);
            l[i] = __float2bfloat16(a[i] - __bfloat162float(h[i]));
        }
        *(uint2*)&g_whi[off] = *(const uint2*)h;
        *(uint2*)&g_wlo[off] = *(const uint2*)l;
    }
}

// ---------------------------------------------------------------------------
// Kernel 3: mma.sync bf16 GEMM, 3-term hi/lo split, fp32 accumulate
//   C[128x128] per CTA = A[128x960] @ W[960x128]; BK=32, 30 chunks
// ---------------------------------------------------------------------------
#define BK   32
#define LDS_ 40   // BK + 8 pad: row stride 80B -> ldmatrix conflict-free

__global__ __launch_bounds__(256)
void kpconv_mma_gemm(float* __restrict__ out)
{
    __shared__ __align__(16) __nv_bfloat16 sAh[128][LDS_];
    __shared__ __align__(16) __nv_bfloat16 sAl[128][LDS_];
    __shared__ __align__(16) __nv_bfloat16 sBh[128][LDS_];
    __shared__ __align__(16) __nv_bfloat16 sBl[128][LDS_];

    const int tid  = threadIdx.x;
    const int wid  = tid >> 5, lane = tid & 31;
    const int wm   = wid & 3;        // warp m-offset: wm*32
    const int wn   = wid >> 2;       // warp n-offset: wn*64
    const size_t rowBase = (size_t)blockIdx.x * 128;

    float acc[2][8][4];
    #pragma unroll
    for (int i = 0; i < 2; i++)
        #pragma unroll
        for (int j = 0; j < 8; j++)
            #pragma unroll
            for (int q = 0; q < 4; q++) acc[i][j][q] = 0.0f;

    // per-lane ldmatrix row/col patterns
    const int ltile = lane >> 3, lr = lane & 7;
    // A: tile0=[m0-7,k0-7] tile1=[m8-15,k0-7] tile2=[m0-7,k8-15] tile3=[m8-15,k8-15]
    const int aRow = (ltile & 1) * 8 + lr;
    const int aCol = (ltile >> 1) * 8;
    // B groups: tile0=[n0-7,k0-7] tile1=[n0-7,k8-15] tile2=[n8-15,k0-7] tile3=[n8-15,k8-15]
    const int bRow = (ltile >> 1) * 8 + lr;
    const int bCol = (ltile & 1) * 8;

    for (int c = 0; c < KTOT / BK; ++c) {
        #pragma unroll
        for (int i = 0; i < 2; ++i) {
            const int idx = tid + i * 256;
            const int r = idx >> 2, seg = idx & 3;
            const size_t gA = (rowBase + r) * KTOT + c * BK + seg * 8;
            *(uint4*)&sAh[r][seg * 8] = *(const uint4*)(g_whi + gA);
            *(uint4*)&sAl[r][seg * 8] = *(const uint4*)(g_wlo + gA);
            const size_t gB = (size_t)r * KTOT + c * BK + seg * 8;
            *(uint4*)&sBh[r][seg * 8] = *(const uint4*)(g_bhi + gB);
            *(uint4*)&sBl[r][seg * 8] = *(const uint4*)(g_blo + gB);
        }
        __syncthreads();

        #pragma unroll
        for (int kk = 0; kk < 2; ++kk) {
            const int kcol = kk * 16;
            // A fragments for both m-tiles (hi & lo)
            uint32_t afh[2][4], afl[2][4];
            #pragma unroll
            for (int mt = 0; mt < 2; ++mt) {
                const int row = wm * 32 + mt * 16 + aRow;
                const int col = kcol + aCol;
                ldsm4(afh[mt][0], afh[mt][1], afh[mt][2], afh[mt][3],
                      smem_u32(&sAh[row][col]));
                ldsm4(afl[mt][0], afl[mt][1], afl[mt][2], afl[mt][3],
                      smem_u32(&sAl[row][col]));
            }
            // B groups: each x4 covers n-tiles (2g, 2g+1) at this kstep
            #pragma unroll
            for (int g = 0; g < 4; ++g) {
                const int row = wn * 64 + g * 16 + bRow;
                const int col = kcol + bCol;
                uint32_t bh[4], bl[4];
                ldsm4(bh[0], bh[1], bh[2], bh[3], smem_u32(&sBh[row][col]));
                ldsm4(bl[0], bl[1], bl[2], bl[3], smem_u32(&sBl[row][col]));
                #pragma unroll
                for (int half = 0; half < 2; ++half) {
                    const int nt = 2 * g + half;
                    #pragma unroll
                    for (int mt = 0; mt < 2; ++mt) {
                        mma16816(acc[mt][nt], afh[mt], bh + 2 * half);
                        mma16816(acc[mt][nt], afl[mt], bh + 2 * half);
                        mma16816(acc[mt][nt], afh[mt], bl + 2 * half);
                    }
                }
            }
        }
        __syncthreads();
    }

    // epilogue: c0:(r,c) c1:(r,c+1) c2:(r+8,c) c3:(r+8,c+1)
    const int bb     = (int)(rowBase >> 14);
    const int mLocal = (int)(rowBase & 16383);
    #pragma unroll
    for (int mt = 0; mt < 2; ++mt)
        #pragma unroll
        for (int nt = 0; nt < 8; ++nt) {
            const int m0 = mLocal + wm * 32 + mt * 16 + (lane >> 2);
            const int n0 = wn * 64 + nt * 8 + 2 * (lane & 3);
            float* o0 = out + ((size_t)bb * DOUT_ + n0) * M_ + m0;
            o0[0]      = acc[mt][nt][0];
            o0[M_]     = acc[mt][nt][1];
            o0[8]      = acc[mt][nt][2];
            o0[M_ + 8] = acc[mt][nt][3];
        }
}

// ---------------------------------------------------------------------------
extern "C" void kernel_launch(void* const* d_in, const int* in_sizes, int n_in,
                              void* d_out, int out_size)
{
    // Dispatch inputs by (pairwise-distinct) element count:
    const float* points_xyz    = nullptr;
    const float* features      = nullptr;
    const float* center_xyz    = nullptr;
    const int*   neighbor_idx  = nullptr;
    const float* kernel_points = nullptr;
    const float* weights       = nullptr;

    for (int i = 0; i < n_in; i++) {
        switch (in_sizes[i]) {
            case 393216:  points_xyz    = (const float*)d_in[i]; break;
            case 8388608: features      = (const float*)d_in[i]; break;
            case 98304:   center_xyz    = (const float*)d_in[i]; break;
            case 1048576: neighbor_idx  = (const int*)d_in[i];   break;
            case 45:      kernel_points = (const float*)d_in[i]; break;
            case 122880:  weights       = (const float*)d_in[i]; break;
            default: break;
        }
    }
    float* out = (float*)d_out;

    dim3 g1(N_ / 32, DIN_ / 32, B_);
    transpose_feat_kernel<<<g1, dim3(32, 8)>>>(features);

    prep_w_kernel<<<(KP_ * DIN_ * DOUT_ + 255) / 256, 256>>>(weights);

    kpconv_weighted_kernel<<<B_ * M_, 256>>>(points_xyz, center_xyz,
                                             neighbor_idx, kernel_points);

    kpconv_mma_gemm<<<(B_ * M_) / 128, 256>>>(out);
}

// round 6
// speedup vs baseline: 2.1927x; 1.5094x over previous
#include <cuda_runtime.h>
#include <cuda_bf16.h>
#include <stdint.h>

#define B_     2
#define N_     65536
#define M_     16384
#define K_     32
#define KP_    15
#define DIN_   64
#define DOUT_  128
#define KTOT   960           // KP_*DIN_
#define SHADOW (-1000.0f)

// ---------------------------------------------------------------------------
// Scratch (__device__ globals per no-allocation rule)
// ---------------------------------------------------------------------------
__device__ float g_featT[(size_t)B_ * N_ * DIN_];                       // 33.5 MB
__device__ __align__(16) __nv_bfloat16 g_whi[(size_t)B_ * M_ * KTOT];   // 60 MB
__device__ __align__(16) __nv_bfloat16 g_wlo[(size_t)B_ * M_ * KTOT];   // 60 MB
__device__ __align__(16) __nv_bfloat16 g_bhi[DOUT_ * KTOT];             // W^T hi
__device__ __align__(16) __nv_bfloat16 g_blo[DOUT_ * KTOT];             // W^T lo

// ---------------------------------------------------------------------------
// helpers
// ---------------------------------------------------------------------------
__device__ __forceinline__ uint32_t smem_u32(const void* p) {
    uint32_t a;
    asm("{ .reg .u64 t; cvta.to.shared.u64 t, %1; cvt.u32.u64 %0, t; }"
        : "=r"(a) : "l"(p));
    return a;
}
__device__ __forceinline__ void ldsm4(uint32_t& r0, uint32_t& r1,
                                      uint32_t& r2, uint32_t& r3, uint32_t addr) {
    asm volatile("ldmatrix.sync.aligned.m8n8.x4.shared.b16 {%0,%1,%2,%3}, [%4];"
                 : "=r"(r0), "=r"(r1), "=r"(r2), "=r"(r3) : "r"(addr));
}
__device__ __forceinline__ void mma16816(float* c, const uint32_t* a,
                                         const uint32_t* b) {
    asm volatile("mma.sync.aligned.m16n8k16.row.col.f32.bf16.bf16.f32 "
                 "{%0,%1,%2,%3}, {%4,%5,%6,%7}, {%8,%9}, {%0,%1,%2,%3};"
                 : "+f"(c[0]), "+f"(c[1]), "+f"(c[2]), "+f"(c[3])
                 : "r"(a[0]), "r"(a[1]), "r"(a[2]), "r"(a[3]),
                   "r"(b[0]), "r"(b[1]));
}
__device__ __forceinline__ void cpasync16(uint32_t dst, const void* src) {
    asm volatile("cp.async.ca.shared.global [%0], [%1], 16;" :: "r"(dst), "l"(src));
}
__device__ __forceinline__ void cp_commit() {
    asm volatile("cp.async.commit_group;" ::: "memory");
}
__device__ __forceinline__ void cp_wait1() {
    asm volatile("cp.async.wait_group 1;" ::: "memory");
}
__device__ __forceinline__ void cp_wait0() {
    asm volatile("cp.async.wait_group 0;" ::: "memory");
}

// ---------------------------------------------------------------------------
// Kernel 1: transpose features [B][Din][N] -> g_featT [B][N][Din]
// ---------------------------------------------------------------------------
__global__ void transpose_feat_kernel(const float* __restrict__ f)
{
    __shared__ float tile[32][33];
    const int b  = blockIdx.z;
    const int n0 = blockIdx.x * 32;
    const int d0 = blockIdx.y * 32;
    const int x = threadIdx.x, y = threadIdx.y;

    #pragma unroll
    for (int i = y; i < 32; i += 8)
        tile[i][x] = f[((size_t)b * DIN_ + (d0 + i)) * N_ + n0 + x];
    __syncthreads();
    #pragma unroll
    for (int i = y; i < 32; i += 8)
        g_featT[((size_t)b * N_ + (n0 + i)) * DIN_ + d0 + x] = tile[x][i];
}

// ---------------------------------------------------------------------------
// Kernel 1b: weights [Kp][Din][Dout] -> g_bhi/g_blo [Dout rows][KTOT cols]
// ---------------------------------------------------------------------------
__global__ void prep_w_kernel(const float* __restrict__ w)
{
    const int e = blockIdx.x * 256 + threadIdx.x;
    if (e >= KP_ * DIN_ * DOUT_) return;
    const int kp = e / DOUT_, o = e % DOUT_;
    const float v = w[e];
    const __nv_bfloat16 hi = __float2bfloat16(v);
    const __nv_bfloat16 lo = __float2bfloat16(v - __bfloat162float(hi));
    g_bhi[o * KTOT + kp] = hi;
    g_blo[o * KTOT + kp] = lo;
}

// ---------------------------------------------------------------------------
// Kernel 2: 16 points per CTA; thread = (point, d4). Feature rows stream
// straight from L2 (one LDG.128 per k, coalesced across the 16 threads);
// acc[15][4] register-blocked over kernel points -> 15x fewer LDS than R5.
// NOTE: neighbor_indices is int32 (JAX canonicalizes int64 -> int32).
// ---------------------------------------------------------------------------
#define PTS 16
__global__ __launch_bounds__(256)
void kpconv_weighted_kernel(const float* __restrict__ points_xyz,
                            const float* __restrict__ center_xyz,
                            const int* __restrict__ nidx,
                            const float* __restrict__ kernel_points)
{
    const int bm0 = blockIdx.x * PTS;
    const int b   = bm0 >> 14;          // 16 | 16384, so one b per block
    const int t   = threadIdx.x;

    __shared__ int   s_idx[PTS][K_];
    __shared__ float s_rx[PTS][K_], s_ry[PTS][K_], s_rz[PTS][K_];
    __shared__ float s_dist[PTS][K_];
    __shared__ float s_w[PTS][481];     // [pt][k*15+p], stride 481 kills conflicts
    __shared__ float s_md[PTS], s_inv[PTS];
    __shared__ float s_kp[KP_ * 3];

    if (t < KP_ * 3) s_kp[t] = kernel_points[t];

    // phase 1: indices, rel coords, dist
    #pragma unroll
    for (int i = 0; i < 2; ++i) {
        const int e  = t + i * 256;
        const int pt = e >> 5, k = e & 31;
        const int bm = bm0 + pt;
        const int ii = nidx[(size_t)bm * K_ + k];
        s_idx[pt][k] = ii;
        float px, py, pz;
        if ((unsigned)ii >= (unsigned)N_) { px = SHADOW; py = SHADOW; pz = SHADOW; }
        else {
            const float* pp = points_xyz + ((size_t)b * N_ + ii) * 3;
            px = pp[0]; py = pp[1]; pz = pp[2];
        }
        const float rx = px - center_xyz[bm * 3 + 0];
        const float ry = py - center_xyz[bm * 3 + 1];
        const float rz = pz - center_xyz[bm * 3 + 2];
        s_rx[pt][k] = rx; s_ry[pt][k] = ry; s_rz[pt][k] = rz;
        s_dist[pt][k] = sqrtf(rx * rx + ry * ry + rz * rz);
    }
    __syncthreads();

    if (t < PTS) {
        float m = 0.0f;
        #pragma unroll
        for (int k = 0; k < K_; ++k) m = fmaxf(m, s_dist[t][k]);
        s_md[t]  = m;
        s_inv[t] = 1.0f / (m / 2.1f + 1e-5f);
    }
    __syncthreads();

    // phase 2: w[pt][k][p] (7680 values, 30 per thread)
    #pragma unroll
    for (int i = 0; i < 30; ++i) {
        const int e  = t + i * 256;
        const int pt = e / 480;
        const int r  = e - pt * 480;
        const int k  = r / 15;
        const int p  = r - k * 15;
        const float md  = s_md[pt];
        const float dx = s_rx[pt][k] - s_kp[p * 3 + 0] * md;
        const float dy = s_ry[pt][k] - s_kp[p * 3 + 1] * md;
        const float dz = s_rz[pt][k] - s_kp[p * 3 + 2] * md;
        const float w  = 1.0f - sqrtf(dx * dx + dy * dy + dz * dz) * s_inv[pt];
        s_w[pt][k * 15 + p] = fmaxf(w, 0.0f);
    }
    __syncthreads();

    // phase 3: accumulate weighted[p][d] in registers
    const int pt = t >> 4, d4 = t & 15;
    float acc[KP_][4];
    #pragma unroll
    for (int p = 0; p < KP_; ++p)
        #pragma unroll
        for (int q = 0; q < 4; ++q) acc[p][q] = 0.0f;

    const float* wrow = s_w[pt];
    #pragma unroll 4
    for (int k = 0; k < K_; ++k) {
        const int ii = s_idx[pt][k];
        if ((unsigned)ii < (unsigned)N_) {
            const float4 f = *(const float4*)(g_featT
                               + ((size_t)b * N_ + ii) * DIN_ + d4 * 4);
            #pragma unroll
            for (int p = 0; p < KP_; ++p) {
                const float wv = wrow[k * 15 + p];
                acc[p][0] += wv * f.x; acc[p][1] += wv * f.y;
                acc[p][2] += wv * f.z; acc[p][3] += wv * f.w;
            }
        }
    }

    // phase 4: bf16 hi/lo split, coalesced 8B stores
    const size_t rowOff = (size_t)(bm0 + pt) * KTOT + d4 * 4;
    #pragma unroll
    for (int p = 0; p < KP_; ++p) {
        __nv_bfloat16 h[4], l[4];
        #pragma unroll
        for (int q = 0; q < 4; ++q) {
            h[q] = __float2bfloat16(acc[p][q]);
            l[q] = __float2bfloat16(acc[p][q] - __bfloat162float(h[q]));
        }
        *(uint2*)&g_whi[rowOff + p * DIN_] = *(const uint2*)h;
        *(uint2*)&g_wlo[rowOff + p * DIN_] = *(const uint2*)l;
    }
}

// ---------------------------------------------------------------------------
// Kernel 3: mma.sync bf16 GEMM, 3-term hi/lo split, cp.async double buffer
//   C[128x128] per CTA = A[128x960] @ W[960x128]; BK=32, 30 chunks
// ---------------------------------------------------------------------------
#define BK    32
#define LDS_  40                 // row stride (elements): 80B, ldsm conflict-free
#define ARR_BYTES  (128 * LDS_ * 2)          // 10240 B per array
#define STAGE_BYTES (4 * ARR_BYTES)          // Ah, Al, Bh, Bl
#define GEMM_SMEM  (2 * STAGE_BYTES)         // 81920 B

__global__ __launch_bounds__(256)
void kpconv_mma_gemm(float* __restrict__ out)
{
    extern __shared__ __align__(16) char sm[];
    const uint32_t smem_base = smem_u32(sm);

    const int tid  = threadIdx.x;
    const int wid  = tid >> 5, lane = tid & 31;
    const int wm   = wid & 3;        // warp m-offset: wm*32
    const int wn   = wid >> 2;       // warp n-offset: wn*64
    const size_t rowBase = (size_t)blockIdx.x * 128;

    // async-copy pattern: 2048 x 16B per stage, 8 per thread
    const int cpIdx0 = tid;          // iterate i: idx = tid + i*256

    auto issue_chunk = [&](int c, int stage) {
        const uint32_t sb = smem_base + stage * STAGE_BYTES;
        #pragma unroll
        for (int i = 0; i < 8; ++i) {
            const int idx = cpIdx0 + i * 256;
            const int arr = idx >> 9;           // 0..3
            const int rem = idx & 511;
            const int row = rem >> 2, seg = rem & 3;
            const uint32_t dst = sb + arr * ARR_BYTES + (row * LDS_ + seg * 8) * 2;
            const __nv_bfloat16* src;
            if (arr == 0)      src = g_whi + (rowBase + row) * KTOT + c * BK + seg * 8;
            else if (arr == 1) src = g_wlo + (rowBase + row) * KTOT + c * BK + seg * 8;
            else if (arr == 2) src = g_bhi + (size_t)row * KTOT + c * BK + seg * 8;
            else               src = g_blo + (size_t)row * KTOT + c * BK + seg * 8;
            cpasync16(dst, src);
        }
        cp_commit();
    };

    float acc[2][8][4];
    #pragma unroll
    for (int i = 0; i < 2; i++)
        #pragma unroll
        for (int j = 0; j < 8; j++)
            #pragma unroll
            for (int q = 0; q < 4; q++) acc[i][j][q] = 0.0f;

    // per-lane ldmatrix row/col patterns
    const int ltile = lane >> 3, lr = lane & 7;
    const int aRow = (ltile & 1) * 8 + lr;
    const int aCol = (ltile >> 1) * 8;
    const int bRow = (ltile >> 1) * 8 + lr;
    const int bCol = (ltile & 1) * 8;

    issue_chunk(0, 0);

    for (int c = 0; c < KTOT / BK; ++c) {
        if (c + 1 < KTOT / BK) { issue_chunk(c + 1, (c + 1) & 1); cp_wait1(); }
        else                   { cp_wait0(); }
        __syncthreads();

        const uint32_t sb  = smem_base + (c & 1) * STAGE_BYTES;
        const uint32_t pAh = sb;
        const uint32_t pAl = sb + ARR_BYTES;
        const uint32_t pBh = sb + 2 * ARR_BYTES;
        const uint32_t pBl = sb + 3 * ARR_BYTES;

        #pragma unroll
        for (int kk = 0; kk < 2; ++kk) {
            const int kcol = kk * 16;
            uint32_t afh[2][4], afl[2][4];
            #pragma unroll
            for (int mt = 0; mt < 2; ++mt) {
                const int row = wm * 32 + mt * 16 + aRow;
                const int col = kcol + aCol;
                const uint32_t off = (uint32_t)(row * LDS_ + col) * 2;
                ldsm4(afh[mt][0], afh[mt][1], afh[mt][2], afh[mt][3], pAh + off);
                ldsm4(afl[mt][0], afl[mt][1], afl[mt][2], afl[mt][3], pAl + off);
            }
            #pragma unroll
            for (int g = 0; g < 4; ++g) {
                const int row = wn * 64 + g * 16 + bRow;
                const int col = kcol + bCol;
                const uint32_t off = (uint32_t)(row * LDS_ + col) * 2;
                uint32_t bh[4], bl[4];
                ldsm4(bh[0], bh[1], bh[2], bh[3], pBh + off);
                ldsm4(bl[0], bl[1], bl[2], bl[3], pBl + off);
                #pragma unroll
                for (int half = 0; half < 2; ++half) {
                    const int nt = 2 * g + half;
                    #pragma unroll
                    for (int mt = 0; mt < 2; ++mt) {
                        mma16816(acc[mt][nt], afh[mt], bh + 2 * half);
                        mma16816(acc[mt][nt], afl[mt], bh + 2 * half);
                        mma16816(acc[mt][nt], afh[mt], bl + 2 * half);
                    }
                }
            }
        }
        __syncthreads();
    }

    // epilogue: c0:(r,c) c1:(r,c+1) c2:(r+8,c) c3:(r+8,c+1)
    const int bb     = (int)(rowBase >> 14);
    const int mLocal = (int)(rowBase & 16383);
    #pragma unroll
    for (int mt = 0; mt < 2; ++mt)
        #pragma unroll
        for (int nt = 0; nt < 8; ++nt) {
            const int m0 = mLocal + wm * 32 + mt * 16 + (lane >> 2);
            const int n0 = wn * 64 + nt * 8 + 2 * (lane & 3);
            float* o0 = out + ((size_t)bb * DOUT_ + n0) * M_ + m0;
            o0[0]      = acc[mt][nt][0];
            o0[M_]     = acc[mt][nt][1];
            o0[8]      = acc[mt][nt][2];
            o0[M_ + 8] = acc[mt][nt][3];
        }
}

// ---------------------------------------------------------------------------
extern "C" void kernel_launch(void* const* d_in, const int* in_sizes, int n_in,
                              void* d_out, int out_size)
{
    // Dispatch inputs by (pairwise-distinct) element count:
    const float* points_xyz    = nullptr;
    const float* features      = nullptr;
    const float* center_xyz    = nullptr;
    const int*   neighbor_idx  = nullptr;
    const float* kernel_points = nullptr;
    const float* weights       = nullptr;

    for (int i = 0; i < n_in; i++) {
        switch (in_sizes[i]) {
            case 393216:  points_xyz    = (const float*)d_in[i]; break;
            case 8388608: features      = (const float*)d_in[i]; break;
            case 98304:   center_xyz    = (const float*)d_in[i]; break;
            case 1048576: neighbor_idx  = (const int*)d_in[i];   break;
            case 45:      kernel_points = (const float*)d_in[i]; break;
            case 122880:  weights       = (const float*)d_in[i]; break;
            default: break;
        }
    }
    float* out = (float*)d_out;

    cudaFuncSetAttribute(kpconv_mma_gemm,
                         cudaFuncAttributeMaxDynamicSharedMemorySize, GEMM_SMEM);

    dim3 g1(N_ / 32, DIN_ / 32, B_);
    transpose_feat_kernel<<<g1, dim3(32, 8)>>>(features);

    prep_w_kernel<<<(KP_ * DIN_ * DOUT_ + 255) / 256, 256>>>(weights);

    kpconv_weighted_kernel<<<(B_ * M_) / PTS, 256>>>(points_xyz, center_xyz,
                                                     neighbor_idx, kernel_points);

    kpconv_mma_gemm<<<(B_ * M_) / 128, 256, GEMM_SMEM>>>(out);
}